// round 6
// baseline (speedup 1.0000x reference)
#include <cuda_runtime.h>
#include <math.h>

#define TPB 256
#define MAXK 128

// Per-block partials: [(b*gx+bx)*4 + {stc,str,cnt,pad}]. Every used slot is
// written each run, so no zeroing kernel is needed.
__device__ float g_part[65536];
// Wrap-around completion counter: returns to 0 after every full run, so graph
// replays are deterministic without an init kernel.
__device__ unsigned g_ctr = 0;

__device__ __forceinline__ float softplusf(float z) {
    return fmaxf(z, 0.f) + log1pf(__expf(-fabsf(z)));  // log(1+exp(z)), stable
}

template<int KFIX>
__global__ __launch_bounds__(TPB) void loss_kernel(
    const float* __restrict__ prop,     // (B, A, 6)
    const float* __restrict__ anchors,  // (A, 4) xywh
    const float* __restrict__ gt,       // (B, K, 4) xywh
    float* __restrict__ out,
    int A, int Krt, int totalBlocks)
{
    const int K = (KFIX > 0) ? KFIX : Krt;
    __shared__ float4 s_g[MAXK];   // gt boxes xyxy
    __shared__ float  s_ga[MAXK];  // gt areas
    __shared__ float  r0[8], r1[8], r2[8];
    __shared__ int    s_last;
    __shared__ float  s_fin[8][4];

    const int b  = blockIdx.y;
    const int gx = gridDim.x;

    for (int k = threadIdx.x; k < K; k += TPB) {
        const float* g = gt + ((size_t)b * K + k) * 4;
        float x0 = g[0], y0 = g[1], w = g[2], h = g[3];
        s_g[k]  = make_float4(x0, y0, x0 + w, y0 + h);
        s_ga[k] = w * h;
    }
    __syncthreads();

    const int a0 = blockIdx.x * (2 * TPB) + threadIdx.x;
    const int a1 = a0 + TPB;
    const int c0 = min(a0, A - 1);
    const int c1 = min(a1, A - 1);

    const float4 an0 = reinterpret_cast<const float4*>(anchors)[c0];
    const float4 an1 = reinterpret_cast<const float4*>(anchors)[c1];

    // Prefetch proposal data (boxes + logit) to hide DRAM latency behind the K-loop.
    const float* p0 = prop + ((size_t)b * A + c0) * 6;
    const float* p1 = prop + ((size_t)b * A + c1) * 6;
    const float2 q01_0 = *reinterpret_cast<const float2*>(p0);
    const float2 q23_0 = *reinterpret_cast<const float2*>(p0 + 2);
    const float  xl_0  = p0[4];
    const float2 q01_1 = *reinterpret_cast<const float2*>(p1);
    const float2 q23_1 = *reinterpret_cast<const float2*>(p1 + 2);
    const float  xl_1  = p1[4];

    const float ax1_0 = an0.x, ay1_0 = an0.y;
    const float ax2_0 = an0.x + an0.z, ay2_0 = an0.y + an0.w;
    const float areaA0 = an0.z * an0.w;
    const float ax1_1 = an1.x, ay1_1 = an1.y;
    const float ax2_1 = an1.x + an1.z, ay2_1 = an1.y + an1.w;
    const float areaA1 = an1.z * an1.w;

    // Running max of approximate IoU; the only loop-carried op is FMNMX.
    // inter = max(w,0)*h: if h<0 then iou<=0 and can't beat best (>=0).
    // No argmax index tracked here — recovered by a pass-2 scan for the rare
    // positive anchors (best >= 0.5) with a bitwise-identical recompute.
    float best0 = 0.f, best1 = 0.f;

#pragma unroll 4
    for (int k = 0; k < K; k++) {
        float4 g = s_g[k];
        float ga = s_ga[k];
        {
            float w = fminf(ax2_0, g.z) - fmaxf(ax1_0, g.x);
            float h = fminf(ay2_0, g.w) - fmaxf(ay1_0, g.y);
            float inter = fmaxf(w, 0.f) * h;
            float denom = (areaA0 + ga) - inter;
            best0 = fmaxf(best0, __fdividef(inter, denom));
        }
        {
            float w = fminf(ax2_1, g.z) - fmaxf(ax1_1, g.x);
            float h = fminf(ay2_1, g.w) - fmaxf(ay1_1, g.y);
            float inter = fmaxf(w, 0.f) * h;
            float denom = (areaA1 + ga) - inter;
            best1 = fmaxf(best1, __fdividef(inter, denom));
        }
    }

    float stc = 0.f, strl = 0.f, cnt = 0.f;

    // ---- epilogue for both anchors (rare-positive pass-2 scan inside) ----
#pragma unroll
    for (int j = 0; j < 2; j++) {
        const int   a     = j ? a1 : a0;
        const float best  = j ? best1 : best0;
        const float ax1   = j ? ax1_1 : ax1_0, ay1 = j ? ay1_1 : ay1_0;
        const float ax2   = j ? ax2_1 : ax2_0, ay2 = j ? ay2_1 : ay2_0;
        const float areaA = j ? areaA1 : areaA0;
        const float2 q01  = j ? q01_1 : q01_0;
        const float2 q23  = j ? q23_1 : q23_0;
        const float x     = j ? xl_1 : xl_0;
        if (a >= A) continue;

        const float sig = 1.f / (1.f + __expf(-x));
        if (best >= 0.5f) {
            cnt += 1.f;
            float om = 1.f - sig;
            stc += 0.25f * softplusf(-x) * om * om;     // focal, t=1
            // pass-2: first k whose (identically computed) iou reaches best
            int bK = 0;
            for (int k = 0; k < K; k++) {
                float4 g = s_g[k];
                float w = fminf(ax2, g.z) - fmaxf(ax1, g.x);
                float h = fminf(ay2, g.w) - fmaxf(ay1, g.y);
                float inter = fmaxf(w, 0.f) * h;
                float denom = (areaA + s_ga[k]) - inter;
                if (__fdividef(inter, denom) >= best) { bK = k; break; }
            }
            float4 g = s_g[bK];
            float ew = fmaxf(fminf(q01.x + q23.x, g.z) - fmaxf(q01.x, g.x), 0.f);
            float eh = fmaxf(fminf(q01.y + q23.y, g.w) - fmaxf(q01.y, g.y), 0.f);
            float ei = ew * eh;
            float eiou = ei / ((q23.x * q23.y + s_ga[bK]) - ei);
            strl += -__logf(eiou + 0.01f);
        } else if (best < 0.4f) {
            stc += 0.75f * softplusf(x) * sig * sig;    // focal, t=0
        }
    }

    // block reduction of (stc, strl, cnt)
    const unsigned m = 0xFFFFFFFFu;
#pragma unroll
    for (int o = 16; o; o >>= 1) {
        stc  += __shfl_down_sync(m, stc,  o);
        strl += __shfl_down_sync(m, strl, o);
        cnt  += __shfl_down_sync(m, cnt,  o);
    }
    const int wid = threadIdx.x >> 5, lane = threadIdx.x & 31;
    if (lane == 0) { r0[wid] = stc; r1[wid] = strl; r2[wid] = cnt; }
    __syncthreads();
    if (threadIdx.x == 0) {
        float t0 = 0.f, t1 = 0.f, t2 = 0.f;
#pragma unroll
        for (int i = 0; i < TPB / 32; i++) { t0 += r0[i]; t1 += r1[i]; t2 += r2[i]; }
        int slot = (b * gx + blockIdx.x) * 4;
        g_part[slot + 0] = t0;
        g_part[slot + 1] = t1;
        g_part[slot + 2] = t2;
        __threadfence();
        unsigned old = atomicInc(&g_ctr, (unsigned)(totalBlocks - 1));
        s_last = (old == (unsigned)(totalBlocks - 1)) ? 1 : 0;
    }
    __syncthreads();

    if (s_last) {
        const int B = gridDim.y;
        const int nwarp = TPB / 32;
        if (threadIdx.x < 32) ((float*)s_fin)[threadIdx.x] = 0.f;
        __syncthreads();

        if (B <= nwarp) {
            const int wpb = nwarp / B;            // warps per batch
            const int bb = wid / wpb;
            if (bb < B) {
                float f0 = 0.f, f1 = 0.f, f2 = 0.f;
                for (int blk = lane + 32 * (wid % wpb); blk < gx; blk += 32 * wpb) {
                    int s = (bb * gx + blk) * 4;
                    f0 += g_part[s + 0];
                    f1 += g_part[s + 1];
                    f2 += g_part[s + 2];
                }
#pragma unroll
                for (int o = 16; o; o >>= 1) {
                    f0 += __shfl_down_sync(m, f0, o);
                    f1 += __shfl_down_sync(m, f1, o);
                    f2 += __shfl_down_sync(m, f2, o);
                }
                if (lane == 0) {
                    atomicAdd(&s_fin[bb][0], f0);
                    atomicAdd(&s_fin[bb][1], f1);
                    atomicAdd(&s_fin[bb][2], f2);
                }
            }
            __syncthreads();
            if (threadIdx.x == 0) {
                float t = 0.f;
                for (int bb2 = 0; bb2 < B; bb2++) {
                    float c = s_fin[bb2][2];
                    float safe = (c > 0.f) ? c : 1.f;
                    t += s_fin[bb2][0] / safe;
                    if (c > 0.f) t += s_fin[bb2][1] / safe;
                }
                out[0] = t / (float)B;
            }
        } else if (threadIdx.x == 0) {
            // fallback (B > nwarp): serial, correctness only
            float t = 0.f;
            for (int bb2 = 0; bb2 < B; bb2++) {
                float f0 = 0.f, f1 = 0.f, f2 = 0.f;
                for (int blk = 0; blk < gx; blk++) {
                    int s = (bb2 * gx + blk) * 4;
                    f0 += g_part[s]; f1 += g_part[s + 1]; f2 += g_part[s + 2];
                }
                float safe = (f2 > 0.f) ? f2 : 1.f;
                t += f0 / safe;
                if (f2 > 0.f) t += f1 / safe;
            }
            out[0] = t / (float)B;
        }
    }
}

extern "C" void kernel_launch(void* const* d_in, const int* in_sizes, int n_in,
                              void* d_out, int out_size) {
    const float* prop    = (const float*)d_in[0];  // ss_proposal (B,A,6)
    const float* anchors = (const float*)d_in[1];  // anchors (A,4)
    const float* gt      = (const float*)d_in[2];  // ground_truth (B,K,4)

    const int A = in_sizes[1] / 4;
    const int B = in_sizes[0] / (A * 6);
    const int K = in_sizes[2] / (B * 4);

    const int gx = (A + 2 * TPB - 1) / (2 * TPB);   // 235 for A=120000
    dim3 grid(gx, B);
    const int total = gx * B;

    if (K == 64)
        loss_kernel<64><<<grid, TPB>>>(prop, anchors, gt, (float*)d_out, A, K, total);
    else
        loss_kernel<0><<<grid, TPB>>>(prop, anchors, gt, (float*)d_out, A, K, total);
}

// round 7
// speedup vs baseline: 1.4396x; 1.4396x over previous
#include <cuda_runtime.h>
#include <math.h>

#define TPB 256
#define MAXK 128

// Per-block partials: [(b*gx+bx)*4 + {stc,str,cnt,pad}]. Every used slot is
// written each run, so no zeroing kernel is needed.
__device__ float g_part[65536];
// Wrap-around completion counter: returns to 0 after every full run, so graph
// replays are deterministic without an init kernel.
__device__ unsigned g_ctr = 0;

#define C4 0.2857142857f      /* 0.4/1.4 */

__device__ __forceinline__ float softplusf(float z) {
    return fmaxf(z, 0.f) + __logf(1.f + __expf(-fabsf(z)));
}

template<int KFIX>
__global__ __launch_bounds__(TPB) void loss_kernel(
    const float* __restrict__ prop,     // (B, A, 6)
    const float* __restrict__ anchors,  // (A, 4) xywh
    const float* __restrict__ gt,       // (B, K, 4) xywh
    float* __restrict__ out,
    int A, int Krt, int totalBlocks)
{
    const int K = (KFIX > 0) ? KFIX : Krt;
    __shared__ float4 s_g[MAXK];          // gt boxes xyxy
    __shared__ float  s_ga[MAXK];         // gt areas
    __shared__ float4 s_g4v[MAXK / 4];    // (2/7)*ga packed 4-per-float4
    __shared__ int    s_q[2 * TPB];       // candidate anchor ids
    __shared__ int    s_qc;
    __shared__ float  r0[8], r1[8], r2[8];
    __shared__ int    s_last;
    __shared__ float  s_fin[8][4];

    const int b  = blockIdx.y;
    const int gx = gridDim.x;

    if (threadIdx.x == 0) s_qc = 0;
    for (int k = threadIdx.x; k < K; k += TPB) {
        const float* g = gt + ((size_t)b * K + k) * 4;
        float x0 = g[0], y0 = g[1], w = g[2], h = g[3];
        s_g[k]  = make_float4(x0, y0, x0 + w, y0 + h);
        float ga = w * h;
        s_ga[k] = ga;
        ((float*)s_g4v)[k] = C4 * ga;
    }
    __syncthreads();

    const int a0 = blockIdx.x * (2 * TPB) + threadIdx.x;
    const int a1 = a0 + TPB;
    const int c0 = min(a0, A - 1);
    const int c1 = min(a1, A - 1);

    const float4 an0 = reinterpret_cast<const float4*>(anchors)[c0];
    const float4 an1 = reinterpret_cast<const float4*>(anchors)[c1];
    // prefetch logits (hide behind hot loop)
    const float xl0 = __ldg(prop + ((size_t)b * A + c0) * 6 + 4);
    const float xl1 = __ldg(prop + ((size_t)b * A + c1) * 6 + 4);

    const float ax1_0 = an0.x, ay1_0 = an0.y;
    const float ax2_0 = an0.x + an0.z, ay2_0 = an0.y + an0.w;
    const float areaA0 = an0.z * an0.w;
    const float ax1_1 = an1.x, ay1_1 = an1.y;
    const float ax2_1 = an1.x + an1.z, ay2_1 = an1.y + an1.w;
    const float areaA1 = an1.z * an1.w;

    // Screen: M4 = max_k( inter_k - (2/7)*ga_k ).
    //   neg  <=> M4 <  (2/7)*areaA     (iou < 0.4 for all k, modulo fp fuzz)
    //   cand <=> M4 >= 0.3330*areaA    (superset of pos: pos => M4 >= areaA/3 + ga/21)
    // inter = max(w,0)*h: if h<0 then inter<=0, harmless under max.
    float M4_0 = -1e30f, M4_1 = -1e30f;

    if (KFIX == 64) {
#pragma unroll 2
        for (int k4 = 0; k4 < 16; k4++) {
            float4 gv = s_g4v[k4];
#pragma unroll
            for (int i = 0; i < 4; i++) {
                float4 g = s_g[k4 * 4 + i];
                float g4 = (i == 0) ? gv.x : (i == 1) ? gv.y : (i == 2) ? gv.z : gv.w;
                {
                    float w = fminf(ax2_0, g.z) - fmaxf(ax1_0, g.x);
                    float h = fminf(ay2_0, g.w) - fmaxf(ay1_0, g.y);
                    float inter = fmaxf(w, 0.f) * h;
                    M4_0 = fmaxf(M4_0, inter - g4);
                }
                {
                    float w = fminf(ax2_1, g.z) - fmaxf(ax1_1, g.x);
                    float h = fminf(ay2_1, g.w) - fmaxf(ay1_1, g.y);
                    float inter = fmaxf(w, 0.f) * h;
                    M4_1 = fmaxf(M4_1, inter - g4);
                }
            }
        }
    } else {
        for (int k = 0; k < K; k++) {
            float4 g = s_g[k];
            float g4 = ((float*)s_g4v)[k];
            {
                float w = fminf(ax2_0, g.z) - fmaxf(ax1_0, g.x);
                float h = fminf(ay2_0, g.w) - fmaxf(ay1_0, g.y);
                M4_0 = fmaxf(M4_0, fmaxf(w, 0.f) * h - g4);
            }
            {
                float w = fminf(ax2_1, g.z) - fmaxf(ax1_1, g.x);
                float h = fminf(ay2_1, g.w) - fmaxf(ay1_1, g.y);
                M4_1 = fmaxf(M4_1, fmaxf(w, 0.f) * h - g4);
            }
        }
    }

    float stc = 0.f, strl = 0.f, cnt = 0.f;

    // classify: negatives inline, candidates to the queue
#pragma unroll
    for (int j = 0; j < 2; j++) {
        const int   a     = j ? a1 : a0;
        const float M4    = j ? M4_1 : M4_0;
        const float areaA = j ? areaA1 : areaA0;
        const float x     = j ? xl1 : xl0;
        if (a >= A) continue;
        if (M4 < C4 * areaA) {
            float sig = 1.f / (1.f + __expf(-x));
            stc += 0.75f * softplusf(x) * sig * sig;        // focal, t=0
        } else if (M4 >= 0.3330f * areaA) {
            int slot = atomicAdd(&s_qc, 1);
            s_q[slot] = a;
        }
        // else: ignore band, contributes nothing
    }
    __syncthreads();

    // pass-2: exact classification + argmax for candidates (dense, contiguous)
    const int qc = s_qc;
    for (int i = threadIdx.x; i < qc; i += TPB) {
        const int a = s_q[i];
        const float4 an = reinterpret_cast<const float4*>(anchors)[a];
        const float ax1 = an.x, ay1 = an.y;
        const float ax2 = an.x + an.z, ay2 = an.y + an.w;
        const float areaA = an.z * an.w;

        // division-free exact argmax (strict > keeps first max), as in the
        // previously-verified kernel (rel_err 6.6e-8)
        float bI = 0.f, bS = 1.f; int bK = 0;
        for (int k = 0; k < K; k++) {
            float4 g = s_g[k];
            float w = fminf(ax2, g.z) - fmaxf(ax1, g.x);
            float h = fminf(ay2, g.w) - fmaxf(ay1, g.y);
            float inter = fmaxf(w, 0.f) * h;
            float S = areaA + s_ga[k];
            bool c = inter * bS > bI * S;
            bI = c ? inter : bI;
            bS = c ? S : bS;
            bK = c ? k : bK;
        }
        const float ts = bI / (bS - bI);

        const float* p = prop + ((size_t)b * A + a) * 6;
        const float x = p[4];
        const float sig = 1.f / (1.f + __expf(-x));
        if (ts >= 0.5f) {
            cnt += 1.f;
            float om = 1.f - sig;
            stc += 0.25f * softplusf(-x) * om * om;         // focal, t=1
            float2 q01 = *reinterpret_cast<const float2*>(p);
            float2 q23 = *reinterpret_cast<const float2*>(p + 2);
            float4 g = s_g[bK];
            float ew = fmaxf(fminf(q01.x + q23.x, g.z) - fmaxf(q01.x, g.x), 0.f);
            float eh = fmaxf(fminf(q01.y + q23.y, g.w) - fmaxf(q01.y, g.y), 0.f);
            float ei = ew * eh;
            float eiou = ei / ((q23.x * q23.y + s_ga[bK]) - ei);
            strl += -__logf(eiou + 0.01f);
        } else if (ts < 0.4f) {
            stc += 0.75f * softplusf(x) * sig * sig;        // focal, t=0
        }
    }

    // block reduction of (stc, strl, cnt)
    const unsigned m = 0xFFFFFFFFu;
#pragma unroll
    for (int o = 16; o; o >>= 1) {
        stc  += __shfl_down_sync(m, stc,  o);
        strl += __shfl_down_sync(m, strl, o);
        cnt  += __shfl_down_sync(m, cnt,  o);
    }
    const int wid = threadIdx.x >> 5, lane = threadIdx.x & 31;
    if (lane == 0) { r0[wid] = stc; r1[wid] = strl; r2[wid] = cnt; }
    __syncthreads();
    if (threadIdx.x == 0) {
        float t0 = 0.f, t1 = 0.f, t2 = 0.f;
#pragma unroll
        for (int i = 0; i < TPB / 32; i++) { t0 += r0[i]; t1 += r1[i]; t2 += r2[i]; }
        int slot = (b * gx + blockIdx.x) * 4;
        g_part[slot + 0] = t0;
        g_part[slot + 1] = t1;
        g_part[slot + 2] = t2;
        __threadfence();
        unsigned old = atomicInc(&g_ctr, (unsigned)(totalBlocks - 1));
        s_last = (old == (unsigned)(totalBlocks - 1)) ? 1 : 0;
    }
    __syncthreads();

    if (s_last) {
        const int B = gridDim.y;
        const int nwarp = TPB / 32;
        if (threadIdx.x < 32) ((float*)s_fin)[threadIdx.x] = 0.f;
        __syncthreads();

        if (B <= nwarp) {
            const int wpb = nwarp / B;            // warps per batch
            const int bb = wid / wpb;
            if (bb < B) {
                float f0 = 0.f, f1 = 0.f, f2 = 0.f;
                for (int blk = lane + 32 * (wid % wpb); blk < gx; blk += 32 * wpb) {
                    int s = (bb * gx + blk) * 4;
                    f0 += g_part[s + 0];
                    f1 += g_part[s + 1];
                    f2 += g_part[s + 2];
                }
#pragma unroll
                for (int o = 16; o; o >>= 1) {
                    f0 += __shfl_down_sync(m, f0, o);
                    f1 += __shfl_down_sync(m, f1, o);
                    f2 += __shfl_down_sync(m, f2, o);
                }
                if (lane == 0) {
                    atomicAdd(&s_fin[bb][0], f0);
                    atomicAdd(&s_fin[bb][1], f1);
                    atomicAdd(&s_fin[bb][2], f2);
                }
            }
            __syncthreads();
            if (threadIdx.x == 0) {
                float t = 0.f;
                for (int bb2 = 0; bb2 < B; bb2++) {
                    float c = s_fin[bb2][2];
                    float safe = (c > 0.f) ? c : 1.f;
                    t += s_fin[bb2][0] / safe;
                    if (c > 0.f) t += s_fin[bb2][1] / safe;
                }
                out[0] = t / (float)B;
            }
        } else if (threadIdx.x == 0) {
            // fallback (B > nwarp): serial, correctness only
            float t = 0.f;
            for (int bb2 = 0; bb2 < B; bb2++) {
                float f0 = 0.f, f1 = 0.f, f2 = 0.f;
                for (int blk = 0; blk < gx; blk++) {
                    int s = (bb2 * gx + blk) * 4;
                    f0 += g_part[s]; f1 += g_part[s + 1]; f2 += g_part[s + 2];
                }
                float safe = (f2 > 0.f) ? f2 : 1.f;
                t += f0 / safe;
                if (f2 > 0.f) t += f1 / safe;
            }
            out[0] = t / (float)B;
        }
    }
}

extern "C" void kernel_launch(void* const* d_in, const int* in_sizes, int n_in,
                              void* d_out, int out_size) {
    const float* prop    = (const float*)d_in[0];  // ss_proposal (B,A,6)
    const float* anchors = (const float*)d_in[1];  // anchors (A,4)
    const float* gt      = (const float*)d_in[2];  // ground_truth (B,K,4)

    const int A = in_sizes[1] / 4;
    const int B = in_sizes[0] / (A * 6);
    const int K = in_sizes[2] / (B * 4);

    const int gx = (A + 2 * TPB - 1) / (2 * TPB);   // 235 for A=120000
    dim3 grid(gx, B);
    const int total = gx * B;

    if (K == 64)
        loss_kernel<64><<<grid, TPB>>>(prop, anchors, gt, (float*)d_out, A, K, total);
    else
        loss_kernel<0><<<grid, TPB>>>(prop, anchors, gt, (float*)d_out, A, K, total);
}